// round 16
// baseline (speedup 1.0000x reference)
#include <cuda_runtime.h>
#include <cuda.h>
#include <cuda_bf16.h>
#include <cstdint>

// Problem constants
#define BB 2048
#define NN 128
#define DD 512
#define EE 64
#define ROWS (BB*NN)            // 262144
#define EPS 1e-6f
#define CAPACITY 2048.0f

#define TILE_M 128
#define THREADS1 288            // 9 warps: 8 convert, 1 ctrl (x-TMA + B-TMA + MMA)

// ---- tiling: A/x chunks of 32 k (16 chunks), B chunks of 64 k (8 chunks) ----
#define ACH 16
#define BCH 8
#define B_TILE_B (EE*128)       // 8192 per term (64-k B chunk)
#define B_STAGE_B (3*B_TILE_B)  // 24576
#define XS_TILE_B (TILE_M*128)  // 16384 (128 rows x 32 floats, SW128)
#define SMEM_TC (2048 + 2*B_STAGE_B + 3*XS_TILE_B)   // ~100KB

// TMEM columns: D=0..63, A ring at 64: 4 stages x 48 cols (3 terms x 16)
#define TM_D 0
#define TM_A 64
#define TMEM_COLS 256

// idesc: dtype=F32, atype=BF16, btype=BF16, N=64, M=128, K-major both
#define IDESC ((1u<<4)|(1u<<7)|(1u<<10)|((EE/8)<<17)|((TILE_M/16)<<24))

// Scratch (device globals; no allocation allowed)
// g_masked is TRANSPOSED: [n][b] (column-major vs the logical [b][n])
__device__ float g_masked[EE*BB];
__device__ float g_denom[EE];
__device__ int   g_load[EE];
// chunk-major pre-swizzled B image: [BCH][3 terms][64 rows x 128B swizzled]
__device__ __align__(128) char g_wimg[BCH * 3 * B_TILE_B];

#define HAS_TCGEN05 (defined(__CUDA_ARCH_FEAT_SM103_ALL) || defined(__CUDA_ARCH_FEAT_SM100_ALL) || defined(__CUDA_ARCH_FEAT_SM101_ALL))

// ---------------- generic helpers ----------------
__device__ __forceinline__ uint32_t sw128(uint32_t o) { return o ^ ((o >> 3) & 0x70); }

__device__ __forceinline__ uint32_t pack_bf2(__nv_bfloat16 a, __nv_bfloat16 b) {
    __nv_bfloat162 t = __halves2bfloat162(a, b);
    return *reinterpret_cast<uint32_t*>(&t);
}

#if HAS_TCGEN05
// ---------------- tcgen05 / TMA PTX helpers (arch-specific target only) ----------------
__device__ __forceinline__ uint32_t smem_u32(const void* p) {
    uint32_t a;
    asm("{ .reg .u64 t; cvta.to.shared.u64 t, %1; cvt.u32.u64 %0, t; }"
        : "=r"(a) : "l"(p));
    return a;
}
__device__ __forceinline__ uint32_t elect1() {
    uint32_t r;
    asm volatile("{\n\t.reg .pred p;\n\telect.sync _|p, 0xFFFFFFFF;\n\t"
                 "selp.b32 %0, 1, 0, p;\n\t}" : "=r"(r));
    return r;
}
__device__ __forceinline__ uint64_t make_desc_sw128(uint32_t addr) {
    const uint64_t base = (2ull << 61) | (1ull << 46) | (64ull << 32) | (1ull << 16);
    return base | ((uint64_t)(addr >> 4) & 0x3FFF);
}
// TS-mode MMA: A in TMEM, B via SMEM descriptor
__device__ __forceinline__ void mma_ts_f16(uint32_t d, uint32_t a, uint64_t b,
                                           uint32_t idesc, uint32_t en) {
    asm volatile(
        "{\n\t.reg .pred p;\n\tsetp.ne.u32 p, %4, 0;\n\t"
        "tcgen05.mma.cta_group::1.kind::f16 [%0], [%1], %2, %3, {%5,%5,%5,%5}, p;\n\t}"
        :: "r"(d), "r"(a), "l"(b), "r"(idesc), "r"(en), "r"(0u) : "memory");
}
__device__ __forceinline__ void mbar_init(uint32_t a, uint32_t cnt) {
    asm volatile("mbarrier.init.shared.b64 [%0], %1;" :: "r"(a), "r"(cnt) : "memory");
}
__device__ __forceinline__ void mbar_arrive(uint32_t a) {
    asm volatile("mbarrier.arrive.release.cta.shared.b64 _, [%0];" :: "r"(a) : "memory");
}
__device__ __forceinline__ void arrive_expect_tx(uint32_t a, uint32_t bytes) {
    asm volatile("mbarrier.arrive.expect_tx.shared.b64 _, [%0], %1;"
                 :: "r"(a), "r"(bytes) : "memory");
}
__device__ __forceinline__ void bulk_g2s(uint32_t dst, const void* src,
                                         uint32_t bytes, uint32_t mbar) {
    asm volatile("cp.async.bulk.shared::cta.global.mbarrier::complete_tx::bytes "
                 "[%0], [%1], %2, [%3];"
                 :: "r"(dst), "l"(src), "r"(bytes), "r"(mbar) : "memory");
}
__device__ __forceinline__ void tma2d(uint32_t dst, const CUtensorMap* map,
                                      int cx, int cy, uint32_t mbar) {
    asm volatile("cp.async.bulk.tensor.2d.shared::cta.global.tile.mbarrier::complete_tx::bytes "
                 "[%0], [%1, {%2, %3}], [%4];"
                 :: "r"(dst), "l"(map), "r"(cx), "r"(cy), "r"(mbar) : "memory");
}
__device__ __forceinline__ void mbar_wait(uint32_t a, uint32_t parity) {
    uint32_t done;
    asm volatile("{\n\t.reg .pred p;\n\t"
        "mbarrier.try_wait.parity.acquire.cta.shared::cta.b64 p, [%1], %2;\n\t"
        "selp.b32 %0, 1, 0, p;\n\t}" : "=r"(done) : "r"(a), "r"(parity) : "memory");
    while (!done) {
        asm volatile("{\n\t.reg .pred p;\n\t"
            "mbarrier.try_wait.parity.acquire.cta.shared::cta.b64 p, [%1], %2, 0x989680;\n\t"
            "selp.b32 %0, 1, 0, p;\n\t}" : "=r"(done) : "r"(a), "r"(parity) : "memory");
    }
}
__device__ __forceinline__ void t5_commit(uint32_t mb) {
    asm volatile("tcgen05.commit.cta_group::1.mbarrier::arrive::one.shared::cluster.b64 [%0];"
                 :: "r"(mb) : "memory");
}
#define T5_ALLOC(smaddr, n) \
    asm volatile("tcgen05.alloc.cta_group::1.sync.aligned.shared::cta.b32 [%0], %1;" \
                 :: "r"(smaddr), "r"((uint32_t)(n)) : "memory")
#define T5_RELINQ() \
    asm volatile("tcgen05.relinquish_alloc_permit.cta_group::1.sync.aligned;")
#define T5_DEALLOC(t, n) \
    asm volatile("tcgen05.dealloc.cta_group::1.sync.aligned.b32 %0, %1;" :: "r"(t), "r"((uint32_t)(n)))
#define T5_FENCE_AFTER()  asm volatile("tcgen05.fence::after_thread_sync;" ::: "memory")
#define T5_FENCE_BEFORE() asm volatile("tcgen05.fence::before_thread_sync;" ::: "memory")
#define T5_WAIT_LD()      asm volatile("tcgen05.wait::ld.sync.aligned;" ::: "memory")
#define T5_WAIT_ST()      asm volatile("tcgen05.wait::st.sync.aligned;" ::: "memory")

#define STTM8(addr, r) \
    asm volatile("tcgen05.st.sync.aligned.32x32b.x8.b32 [%0], " \
        "{%1,%2,%3,%4,%5,%6,%7,%8};" \
        :: "r"(addr), "r"((r)[0]), "r"((r)[1]), "r"((r)[2]), "r"((r)[3]), \
           "r"((r)[4]), "r"((r)[5]), "r"((r)[6]), "r"((r)[7]) : "memory")

#define LDTM32(r, addr) \
    asm volatile( \
        "tcgen05.ld.sync.aligned.32x32b.x32.b32 " \
        "{%0, %1, %2, %3, %4, %5, %6, %7, " \
        " %8, %9, %10, %11, %12, %13, %14, %15, " \
        " %16, %17, %18, %19, %20, %21, %22, %23, " \
        " %24, %25, %26, %27, %28, %29, %30, %31}, [%32];" \
        : "=r"((r)[0]),  "=r"((r)[1]),  "=r"((r)[2]),  "=r"((r)[3]), \
          "=r"((r)[4]),  "=r"((r)[5]),  "=r"((r)[6]),  "=r"((r)[7]), \
          "=r"((r)[8]),  "=r"((r)[9]),  "=r"((r)[10]), "=r"((r)[11]), \
          "=r"((r)[12]), "=r"((r)[13]), "=r"((r)[14]), "=r"((r)[15]), \
          "=r"((r)[16]), "=r"((r)[17]), "=r"((r)[18]), "=r"((r)[19]), \
          "=r"((r)[20]), "=r"((r)[21]), "=r"((r)[22]), "=r"((r)[23]), \
          "=r"((r)[24]), "=r"((r)[25]), "=r"((r)[26]), "=r"((r)[27]), \
          "=r"((r)[28]), "=r"((r)[29]), "=r"((r)[30]), "=r"((r)[31]) \
        : "r"(addr))
#endif  // HAS_TCGEN05

// ---------------- Kernel 0: build all 3 pre-swizzled W images in one pass ----------------
__global__ void k0_wsplit(const float* __restrict__ w) {
    int i = blockIdx.x * blockDim.x + threadIdx.x;      // 0..4095
    int c = i >> 9, e = (i >> 3) & 63, k16 = i & 7;
    const float4* src = reinterpret_cast<const float4*>(w + (size_t)e * DD + c * 64 + k16 * 8);
    float4 a = src[0], b = src[1];
    float f[8] = {a.x, a.y, a.z, a.w, b.x, b.y, b.z, b.w};
    uint32_t oh[4], om[4], ol[4];
#pragma unroll
    for (int q = 0; q < 4; q++) {
        __nv_bfloat16 h0 = __float2bfloat16(f[q*2]);
        __nv_bfloat16 h1 = __float2bfloat16(f[q*2+1]);
        float r0 = f[q*2]   - __bfloat162float(h0);
        float r1 = f[q*2+1] - __bfloat162float(h1);
        __nv_bfloat16 m0 = __float2bfloat16(r0);
        __nv_bfloat16 m1 = __float2bfloat16(r1);
        float l0 = r0 - __bfloat162float(m0);
        float l1 = r1 - __bfloat162float(m1);
        oh[q] = pack_bf2(h0, h1);
        om[q] = pack_bf2(m0, m1);
        ol[q] = pack_bf2(__float2bfloat16(l0), __float2bfloat16(l1));
    }
    uint32_t sw = sw128((uint32_t)e * 128 + k16 * 16);
    uint32_t base = c * B_STAGE_B;
    *reinterpret_cast<uint4*>(g_wimg + base + 0 * B_TILE_B + sw) = make_uint4(oh[0], oh[1], oh[2], oh[3]);
    *reinterpret_cast<uint4*>(g_wimg + base + 1 * B_TILE_B + sw) = make_uint4(om[0], om[1], om[2], om[3]);
    *reinterpret_cast<uint4*>(g_wimg + base + 2 * B_TILE_B + sw) = make_uint4(ol[0], ol[1], ol[2], ol[3]);
}

// ---------------- Kernel 1: TMA-fed TS GEMM + fused mask/zero-fill ----------------
// One CTA == one batch b (TILE_M == NN).
__global__ __launch_bounds__(THREADS1, 2)
void k1_gemm(const float* __restrict__ x,
             const float* __restrict__ bias,
             float* __restrict__ out,
             const __grid_constant__ CUtensorMap xmap) {
#if HAS_TCGEN05
    extern __shared__ char sm[];
    const uint32_t smem_base = smem_u32(sm);
#define MB_SF(i) (smem_base + 16  + (uint32_t)(i)*8)
#define MB_E(i)  (smem_base + 48  + (uint32_t)(i)*8)
#define MB_BF(i) (smem_base + 80  + (uint32_t)(i)*8)
#define MB_XF(i) (smem_base + 96  + (uint32_t)(i)*8)
#define MB_XR(i) (smem_base + 120 + (uint32_t)(i)*8)
    uint32_t* bitmap = reinterpret_cast<uint32_t*>(sm + 192);   // 2x u32 mask
    float* bias_s = reinterpret_cast<float*>(sm + 256);
    const uint32_t b0_abs = (smem_base + 1024 + 1023) & ~1023u;
    const uint32_t xs_abs = b0_abs + 2 * B_STAGE_B;
    char* xs_ptr = sm + (xs_abs - smem_base);

    const int tid = threadIdx.x;
    const int wid = tid >> 5, lid = tid & 31;
    const int bno = blockIdx.x;                    // batch index
    const long rowbase = (long)bno * TILE_M;

    if (wid == 8) {
        T5_ALLOC(smem_base, TMEM_COLS);
        T5_RELINQ();
    }
    if (tid == 0) {
#pragma unroll
        for (int i = 0; i < 4; i++) { mbar_init(MB_SF(i), 8); mbar_init(MB_E(i), 1); }
        mbar_init(MB_BF(0), 1); mbar_init(MB_BF(1), 1);
#pragma unroll
        for (int i = 0; i < 3; i++) { mbar_init(MB_XF(i), 1); mbar_init(MB_XR(i), 8); }
        bitmap[0] = 0; bitmap[1] = 0;
    }
    if (tid < EE) bias_s[tid] = bias[tid];
    __syncthreads();
    const uint32_t tmem = *reinterpret_cast<uint32_t*>(sm);

    if (wid < 8) {
        // ===== converters: LDS from TMA-staged xs -> 3x bf16 -> TMEM (A ring 4-deep) =====
        const int awid = wid & 3;               // subpartition
        const int kh   = wid >> 2;              // 16-k half of the 32-k chunk
        const int row  = awid * 32 + lid;
        const uint32_t woff = (uint32_t)awid << 21;
        const char* xrow = xs_ptr + row * 128;
        const uint32_t rsw = (uint32_t)(row & 7);

        uint32_t xmask = 0;        // xf parities per xs stage (init 0)
        uint32_t emask = 0xF;      // e parities per A stage (init 1)
        int sx = 0;
        for (int c = 0; c < ACH; c++) {
            const int s = c & 3;
            mbar_wait(MB_XF(sx), (xmask >> sx) & 1); xmask ^= 1u << sx;

            const char* xb = xrow + sx * XS_TILE_B;
            float4 f4[4];
#pragma unroll
            for (int i = 0; i < 4; i++)
                f4[i] = *reinterpret_cast<const float4*>(
                    xb + (((uint32_t)(kh * 4 + i) ^ rsw) << 4));

            // convert fully BEFORE the e-wait (off the critical section)
            uint32_t o0[8], o1[8], o2[8];
#pragma unroll
            for (int i = 0; i < 4; i++) {
                float4 v = f4[i];
#pragma unroll
                for (int p = 0; p < 2; p++) {
                    float a0 = p ? v.z : v.x;
                    float a1 = p ? v.w : v.y;
                    __nv_bfloat162 H = __float22bfloat162_rn(make_float2(a0, a1));
                    float2 Hf = __bfloat1622float2(H);
                    float r0 = a0 - Hf.x, r1 = a1 - Hf.y;
                    __nv_bfloat162 M = __float22bfloat162_rn(make_float2(r0, r1));
                    float2 Mf = __bfloat1622float2(M);
                    __nv_bfloat162 L = __float22bfloat162_rn(make_float2(r0 - Mf.x, r1 - Mf.y));
                    o0[i * 2 + p] = *reinterpret_cast<uint32_t*>(&H);
                    o1[i * 2 + p] = *reinterpret_cast<uint32_t*>(&M);
                    o2[i * 2 + p] = *reinterpret_cast<uint32_t*>(&L);
                }
            }
            __syncwarp();
            if (elect1()) mbar_arrive(MB_XR(sx));          // xs stage free early
            sx = (sx == 2) ? 0 : sx + 1;

            mbar_wait(MB_E(s), (emask >> s) & 1); emask ^= 1u << s;   // A stage free
            const uint32_t acol = tmem + TM_A + s * 48 + woff + kh * 8;
            STTM8(acol + 0,  o0);
            STTM8(acol + 16, o1);
            STTM8(acol + 32, o2);
            T5_WAIT_ST();
            T5_FENCE_BEFORE();
            if (elect1()) mbar_arrive(MB_SF(s));
        }

        // ===== epilogue =====
        if (wid >= 4) {
            // warps 4-7: zero-fill second half of this batch's output slab
            if (out) {
                float4* o4 = reinterpret_cast<float4*>(out) + (size_t)bno * 2048;
                const float4 z = make_float4(0.f, 0.f, 0.f, 0.f);
                const int t = (wid - 4) * 32 + lid;
#pragma unroll
                for (int i = 8; i < 16; i++)
                    o4[i * 128 + t] = z;
            }
        } else {
            // warps 0-3 (128 threads, one per seq position): softmax + mask + first half fill
            const int n = wid * 32 + lid;        // seq position 0..127
            mbar_wait(MB_E(3), 1);
            T5_FENCE_AFTER();

            float vals[EE];
            {
                uint32_t a[32];
                LDTM32(a, tmem + TM_D);
                T5_WAIT_LD();
#pragma unroll
                for (int e = 0; e < 32; e++)
                    vals[e] = __uint_as_float(a[e]) + bias_s[e];
                LDTM32(a, tmem + TM_D + 32);
                T5_WAIT_LD();
#pragma unroll
                for (int e = 0; e < 32; e++)
                    vals[32 + e] = __uint_as_float(a[e]) + bias_s[32 + e];
            }
            T5_FENCE_BEFORE();

            float bv = vals[0];
            int be = 0;
#pragma unroll
            for (int e = 1; e < EE; e++)
                if (vals[e] > bv) { bv = vals[e]; be = e; }
            float s = 0.f;
#pragma unroll
            for (int e = 0; e < EE; e++)
                s += __expf(vals[e] - bv);
            float p0 = __expf(vals[0] - bv) / s;

            // fused k2: membership bitmap over argmax values (be < 64)
            atomicOr(&bitmap[be >> 5], 1u << (be & 31));
            asm volatile("bar.sync 1, 128;" ::: "memory");

            if (n < EE) {
                uint32_t bit = (bitmap[n >> 5] >> (n & 31)) & 1u;
                // transposed layout [n][b] for coalesced k34 reads
                g_masked[(size_t)n * BB + bno] = bit ? p0 : 0.f;
            }

            // first half of the zero-fill
            if (out) {
                float4* o4 = reinterpret_cast<float4*>(out) + (size_t)bno * 2048;
                const float4 z = make_float4(0.f, 0.f, 0.f, 0.f);
                const int t = wid * 32 + lid;
#pragma unroll
                for (int i = 0; i < 8; i++)
                    o4[i * 128 + t] = z;
            }
        }
    } else {
        // ===== ctrl warp (wid 8): x 2D-TMA + B bulk TMA + MMA =====
        if (elect1()) {
            const int rb32 = (int)rowbase;
            // prologue: stage x chunks 0..2 and B chunks 0..1
#pragma unroll
            for (int p = 0; p < 3; p++) {
                arrive_expect_tx(MB_XF(p), XS_TILE_B);
                tma2d(xs_abs + p * XS_TILE_B, &xmap, p * 32, rb32, MB_XF(p));
            }
            arrive_expect_tx(MB_BF(0), B_STAGE_B);
            bulk_g2s(b0_abs, g_wimg, B_STAGE_B, MB_BF(0));
            arrive_expect_tx(MB_BF(1), B_STAGE_B);
            bulk_g2s(b0_abs + B_STAGE_B, g_wimg + B_STAGE_B, B_STAGE_B, MB_BF(1));

            uint64_t bd0[3], bd1[3];
#pragma unroll
            for (int t = 0; t < 3; t++) {
                bd0[t] = make_desc_sw128(b0_abs + t * B_TILE_B);
                bd1[t] = make_desc_sw128(b0_abs + B_STAGE_B + t * B_TILE_B);
            }
            const int ta[6] = {0, 0, 1, 1, 0, 2};
            const int tb[6] = {0, 1, 0, 1, 2, 0};

            uint32_t smask = 0;    // sf parities (init 0)
            uint32_t bmask = 0;    // bf parities (init 0)
            uint32_t xrmask = 0;   // xr parities (init 0)
            uint32_t ebmask = 0;   // e parities for B-prefetch (stages 1,3; init 0)
            for (int c = 0; c < ACH; c++) {
                const int s  = c & 3;
                const int cb = c >> 1;

                mbar_wait(MB_SF(s), (smask >> s) & 1); smask ^= 1u << s;
                if ((c & 1) == 0) {
                    const int bs = cb & 1;
                    mbar_wait(MB_BF(bs), (bmask >> bs) & 1); bmask ^= 1u << bs;
                }
                T5_FENCE_AFTER();

                const uint32_t abase = tmem + TM_A + s * 48;
                const uint64_t* bd = (cb & 1) ? bd1 : bd0;
                const int koff = (c & 1) * 4;
#pragma unroll
                for (int ks = 0; ks < 2; ks++) {
#pragma unroll
                    for (int t = 0; t < 6; t++) {
                        uint32_t a = abase + ta[t] * 16 + ks * 8;
                        uint64_t b = bd[tb[t]] + koff + ks * 2;
                        uint32_t en = !(c == 0 && ks == 0 && t == 0);
                        mma_ts_f16(tmem + TM_D, a, b, IDESC, en);
                    }
                }
                t5_commit(MB_E(s));

                // x prefetch chunk c+3 into stage c%3 (xr(c) already arrived: sf(c) done)
                if (c + 3 < ACH) {
                    const int sx = c % 3;
                    mbar_wait(MB_XR(sx), (xrmask >> sx) & 1); xrmask ^= 1u << sx;
                    arrive_expect_tx(MB_XF(sx), XS_TILE_B);
                    tma2d(xs_abs + sx * XS_TILE_B, &xmap, (c + 3) * 32, rb32, MB_XF(sx));
                }

                // B prefetch (2 A-chunks of lead)
                if ((c & 1) == 0 && c + 2 < ACH) {
                    const int cbn = cb + 1;
                    if (cbn >= 2) {
                        const int es = (c - 1) & 3;          // 1 or 3
                        const int ei = (es == 1) ? 0 : 1;
                        mbar_wait(MB_E(es), (ebmask >> ei) & 1); ebmask ^= 1u << ei;
                        arrive_expect_tx(MB_BF(cbn & 1), B_STAGE_B);
                        bulk_g2s(b0_abs + (cbn & 1) * B_STAGE_B,
                                 g_wimg + cbn * B_STAGE_B, B_STAGE_B, MB_BF(cbn & 1));
                    }
                }
            }
        }
    }

    __syncthreads();
    if (wid == 8) {
        T5_DEALLOC(tmem, TMEM_COLS);
    }
#else
    // ---------------- portable fallback (generic-PTX compile phase only) ----------------
    __shared__ uint32_t fb_bitmap[2];
    __shared__ float fb_p0[TILE_M];
    const int tid = threadIdx.x;
    const int bno = blockIdx.x;
    if (tid == 0) { fb_bitmap[0] = 0; fb_bitmap[1] = 0; }
    __syncthreads();
    if (tid < TILE_M) {
        fb_p0[tid] = 0.f;
        atomicOr(&fb_bitmap[0], 1u);
    }
    __syncthreads();
    if (tid < EE) g_masked[(size_t)tid * BB + bno] = fb_p0[tid];
    if (out && tid < TILE_M) {
        float4* o4 = reinterpret_cast<float4*>(out) + (size_t)bno * 2048;
        const float4 z = make_float4(0.f, 0.f, 0.f, 0.f);
        for (int i = 0; i < 16; i++) o4[i * 128 + tid] = z;
    }
    (void)x; (void)bias;
#endif
}

// ---------------- Kernel 34: fused column reduce + sparse scatter ----------------
// One block per expert-column n. Coalesced read of g_masked[n][*], tree-reduce
// (same order as the old k3 -> bit-identical denom), one divide per block,
// then 8 scattered stores per thread from registers.
__global__ void k34_denom_scatter(float* __restrict__ out) {
    __shared__ float sv[256];
    __shared__ int   sc[256];
    __shared__ float sscale;
    const int n = blockIdx.x;
    const int t = threadIdx.x;

    float m[8];
    float s = 0.f;
    int cnt = 0;
#pragma unroll
    for (int k = 0; k < BB / 256; k++) {
        m[k] = g_masked[(size_t)n * BB + t + k * 256];
        s += m[k];
        cnt += (m[k] > 0.f);
    }
    sv[t] = s; sc[t] = cnt;
    __syncthreads();
    for (int off = 128; off >= 1; off >>= 1) {
        if (t < off) { sv[t] += sv[t + off]; sc[t] += sc[t + off]; }
        __syncthreads();
    }
    if (t == 0) {
        float dn = sv[0] + EPS;
        g_denom[n] = dn;
        g_load[n]  = sc[0];
        sscale = CAPACITY / dn;
    }
    __syncthreads();

    if (out) {
        const float scale = sscale;
#pragma unroll
        for (int k = 0; k < BB / 256; k++) {
            int b = t + k * 256;
            out[((size_t)b * NN + n) * EE] = m[k] * scale;
        }
    }
}

// ---------------- Kernel 5: loss (parallel divides, fixed-order sum) ----------------
__global__ void k5_loss(float* __restrict__ lossptr) {
    __shared__ double simp[EE], simp2[EE], sld[EE], sld2[EE];
    int t = threadIdx.x;
    if (t < EE) {
        double dn = (double)g_denom[t];
        double S  = dn - (double)EPS;
        double imp = (double)CAPACITY * S / dn;
        simp[t]  = imp;
        simp2[t] = imp * imp;
        double ld = (double)g_load[t];
        sld[t]  = ld;
        sld2[t] = ld * ld;
    }
    __syncthreads();
    if (t == 0) {
        double si = 0.0, si2 = 0.0, sl = 0.0, sl2 = 0.0;
        for (int q = 0; q < EE; q++) {
            si += simp[q]; si2 += simp2[q];
            sl += sld[q];  sl2 += sld2[q];
        }
        const double M = (double)(NN * EE);
        double mean_i = si / M;
        double var_i  = (si2 - si * si / M) / (M - 1.0);
        double cv_i   = var_i / (mean_i * mean_i + 1e-10);
        double mean_l = sl / M;
        double var_l  = (sl2 - sl * sl / M) / (M - 1.0);
        double cv_l   = var_l / (mean_l * mean_l + 1e-10);
        *lossptr = (float)(cv_i + cv_l);
    }
}

// host-side tensor map encode via driver entry point (no -lcuda link needed)
typedef CUresult (*EncodeTiledFn)(
    CUtensorMap*, CUtensorMapDataType, cuuint32_t, void*,
    const cuuint64_t*, const cuuint64_t*, const cuuint32_t*, const cuuint32_t*,
    CUtensorMapInterleave, CUtensorMapSwizzle, CUtensorMapL2promotion,
    CUtensorMapFloatOOBfill);

extern "C" void kernel_launch(void* const* d_in, const int* in_sizes, int n_in,
                              void* d_out, int out_size) {
    const float* x    = (const float*)d_in[0];
    const float* w    = (const float*)d_in[1];
    const float* bias = (const float*)d_in[2];
    float* out = (float*)d_out;

    const long total = (long)BB * NN * EE;        // 16777216
    float* gs_out = ((long)out_size >= total) ? out : nullptr;

    // Build the x tensor map: fp32 [512 x 262144], box [32 x 128], SW128.
    CUtensorMap xmap;
    {
        EncodeTiledFn fn = nullptr;
        cudaDriverEntryPointQueryResult qres;
        cudaGetDriverEntryPoint("cuTensorMapEncodeTiled", (void**)&fn,
                                cudaEnableDefault, &qres);
        cuuint64_t dims[2]    = {DD, ROWS};
        cuuint64_t strides[1] = {DD * sizeof(float)};
        cuuint32_t box[2]     = {32, TILE_M};
        cuuint32_t estr[2]    = {1, 1};
        fn(&xmap, CU_TENSOR_MAP_DATA_TYPE_FLOAT32, 2, (void*)x,
           dims, strides, box, estr,
           CU_TENSOR_MAP_INTERLEAVE_NONE, CU_TENSOR_MAP_SWIZZLE_128B,
           CU_TENSOR_MAP_L2_PROMOTION_L2_128B, CU_TENSOR_MAP_FLOAT_OOB_FILL_NONE);
    }

    cudaFuncSetAttribute(k1_gemm, cudaFuncAttributeMaxDynamicSharedMemorySize, SMEM_TC);

    // 4 launches per iteration: k0, k1, k34, k5
    k0_wsplit<<<16, 256>>>(w);
    k1_gemm<<<ROWS / TILE_M, THREADS1, SMEM_TC>>>(x, bias, gs_out, xmap);
    k34_denom_scatter<<<EE, 256>>>(gs_out);

    if (gs_out) {
        if ((long)out_size > total) {
            k5_loss<<<1, 64>>>(out + total);
        }
    } else {
        k5_loss<<<1, 64>>>(out);
    }
}

// round 17
// speedup vs baseline: 1.0453x; 1.0453x over previous
#include <cuda_runtime.h>
#include <cuda.h>
#include <cuda_bf16.h>
#include <cstdint>

// Problem constants
#define BB 2048
#define NN 128
#define DD 512
#define EE 64
#define ROWS (BB*NN)            // 262144
#define EPS 1e-6f
#define CAPACITY 2048.0f

#define TILE_M 128
#define THREADS1 288            // 9 warps: 8 convert, 1 ctrl (x-TMA + B-TMA + MMA)

// ---- tiling: A/x chunks of 32 k (16 chunks), B chunks of 64 k (8 chunks) ----
#define ACH 16
#define BCH 8
#define B_TILE_B (EE*128)       // 8192 per term (64-k B chunk)
#define B_STAGE_B (3*B_TILE_B)  // 24576
#define XS_TILE_B (TILE_M*128)  // 16384 (128 rows x 32 floats, SW128)
#define SMEM_TC (2048 + 2*B_STAGE_B + 3*XS_TILE_B)   // ~100KB

// TMEM columns: D=0..63, A ring at 64: 4 stages x 48 cols (3 terms x 16)
#define TM_D 0
#define TM_A 64
#define TMEM_COLS 256

// idesc: dtype=F32, atype=BF16, btype=BF16, N=64, M=128, K-major both
#define IDESC ((1u<<4)|(1u<<7)|(1u<<10)|((EE/8)<<17)|((TILE_M/16)<<24))

// Scratch (device globals; no allocation allowed)
// g_masked is TRANSPOSED: [n][b]
__device__ float g_masked[EE*BB];
__device__ float g_denom[EE];
__device__ int   g_load[EE];
__device__ int   g_done;
// chunk-major pre-swizzled B image: [BCH][3 terms][64 rows x 128B swizzled]
__device__ __align__(128) char g_wimg[BCH * 3 * B_TILE_B];

#define HAS_TCGEN05 (defined(__CUDA_ARCH_FEAT_SM103_ALL) || defined(__CUDA_ARCH_FEAT_SM100_ALL) || defined(__CUDA_ARCH_FEAT_SM101_ALL))

// ---------------- generic helpers ----------------
__device__ __forceinline__ uint32_t sw128(uint32_t o) { return o ^ ((o >> 3) & 0x70); }

__device__ __forceinline__ uint32_t pack_bf2(__nv_bfloat16 a, __nv_bfloat16 b) {
    __nv_bfloat162 t = __halves2bfloat162(a, b);
    return *reinterpret_cast<uint32_t*>(&t);
}

#if HAS_TCGEN05
// ---------------- tcgen05 / TMA PTX helpers (arch-specific target only) ----------------
__device__ __forceinline__ uint32_t smem_u32(const void* p) {
    uint32_t a;
    asm("{ .reg .u64 t; cvta.to.shared.u64 t, %1; cvt.u32.u64 %0, t; }"
        : "=r"(a) : "l"(p));
    return a;
}
__device__ __forceinline__ uint32_t elect1() {
    uint32_t r;
    asm volatile("{\n\t.reg .pred p;\n\telect.sync _|p, 0xFFFFFFFF;\n\t"
                 "selp.b32 %0, 1, 0, p;\n\t}" : "=r"(r));
    return r;
}
__device__ __forceinline__ uint64_t make_desc_sw128(uint32_t addr) {
    const uint64_t base = (2ull << 61) | (1ull << 46) | (64ull << 32) | (1ull << 16);
    return base | ((uint64_t)(addr >> 4) & 0x3FFF);
}
// TS-mode MMA: A in TMEM, B via SMEM descriptor
__device__ __forceinline__ void mma_ts_f16(uint32_t d, uint32_t a, uint64_t b,
                                           uint32_t idesc, uint32_t en) {
    asm volatile(
        "{\n\t.reg .pred p;\n\tsetp.ne.u32 p, %4, 0;\n\t"
        "tcgen05.mma.cta_group::1.kind::f16 [%0], [%1], %2, %3, {%5,%5,%5,%5}, p;\n\t}"
        :: "r"(d), "r"(a), "l"(b), "r"(idesc), "r"(en), "r"(0u) : "memory");
}
__device__ __forceinline__ void mbar_init(uint32_t a, uint32_t cnt) {
    asm volatile("mbarrier.init.shared.b64 [%0], %1;" :: "r"(a), "r"(cnt) : "memory");
}
__device__ __forceinline__ void mbar_arrive(uint32_t a) {
    asm volatile("mbarrier.arrive.release.cta.shared.b64 _, [%0];" :: "r"(a) : "memory");
}
__device__ __forceinline__ void arrive_expect_tx(uint32_t a, uint32_t bytes) {
    asm volatile("mbarrier.arrive.expect_tx.shared.b64 _, [%0], %1;"
                 :: "r"(a), "r"(bytes) : "memory");
}
__device__ __forceinline__ void bulk_g2s(uint32_t dst, const void* src,
                                         uint32_t bytes, uint32_t mbar) {
    asm volatile("cp.async.bulk.shared::cta.global.mbarrier::complete_tx::bytes "
                 "[%0], [%1], %2, [%3];"
                 :: "r"(dst), "l"(src), "r"(bytes), "r"(mbar) : "memory");
}
__device__ __forceinline__ void tma2d(uint32_t dst, const CUtensorMap* map,
                                      int cx, int cy, uint32_t mbar) {
    asm volatile("cp.async.bulk.tensor.2d.shared::cta.global.tile.mbarrier::complete_tx::bytes "
                 "[%0], [%1, {%2, %3}], [%4];"
                 :: "r"(dst), "l"(map), "r"(cx), "r"(cy), "r"(mbar) : "memory");
}
__device__ __forceinline__ void mbar_wait(uint32_t a, uint32_t parity) {
    uint32_t done;
    asm volatile("{\n\t.reg .pred p;\n\t"
        "mbarrier.try_wait.parity.acquire.cta.shared::cta.b64 p, [%1], %2;\n\t"
        "selp.b32 %0, 1, 0, p;\n\t}" : "=r"(done) : "r"(a), "r"(parity) : "memory");
    while (!done) {
        asm volatile("{\n\t.reg .pred p;\n\t"
            "mbarrier.try_wait.parity.acquire.cta.shared::cta.b64 p, [%1], %2, 0x989680;\n\t"
            "selp.b32 %0, 1, 0, p;\n\t}" : "=r"(done) : "r"(a), "r"(parity) : "memory");
    }
}
__device__ __forceinline__ void t5_commit(uint32_t mb) {
    asm volatile("tcgen05.commit.cta_group::1.mbarrier::arrive::one.shared::cluster.b64 [%0];"
                 :: "r"(mb) : "memory");
}
#define T5_ALLOC(smaddr, n) \
    asm volatile("tcgen05.alloc.cta_group::1.sync.aligned.shared::cta.b32 [%0], %1;" \
                 :: "r"(smaddr), "r"((uint32_t)(n)) : "memory")
#define T5_RELINQ() \
    asm volatile("tcgen05.relinquish_alloc_permit.cta_group::1.sync.aligned;")
#define T5_DEALLOC(t, n) \
    asm volatile("tcgen05.dealloc.cta_group::1.sync.aligned.b32 %0, %1;" :: "r"(t), "r"((uint32_t)(n)))
#define T5_FENCE_AFTER()  asm volatile("tcgen05.fence::after_thread_sync;" ::: "memory")
#define T5_FENCE_BEFORE() asm volatile("tcgen05.fence::before_thread_sync;" ::: "memory")
#define T5_WAIT_LD()      asm volatile("tcgen05.wait::ld.sync.aligned;" ::: "memory")
#define T5_WAIT_ST()      asm volatile("tcgen05.wait::st.sync.aligned;" ::: "memory")

#define STTM8(addr, r) \
    asm volatile("tcgen05.st.sync.aligned.32x32b.x8.b32 [%0], " \
        "{%1,%2,%3,%4,%5,%6,%7,%8};" \
        :: "r"(addr), "r"((r)[0]), "r"((r)[1]), "r"((r)[2]), "r"((r)[3]), \
           "r"((r)[4]), "r"((r)[5]), "r"((r)[6]), "r"((r)[7]) : "memory")

#define LDTM32(r, addr) \
    asm volatile( \
        "tcgen05.ld.sync.aligned.32x32b.x32.b32 " \
        "{%0, %1, %2, %3, %4, %5, %6, %7, " \
        " %8, %9, %10, %11, %12, %13, %14, %15, " \
        " %16, %17, %18, %19, %20, %21, %22, %23, " \
        " %24, %25, %26, %27, %28, %29, %30, %31}, [%32];" \
        : "=r"((r)[0]),  "=r"((r)[1]),  "=r"((r)[2]),  "=r"((r)[3]), \
          "=r"((r)[4]),  "=r"((r)[5]),  "=r"((r)[6]),  "=r"((r)[7]), \
          "=r"((r)[8]),  "=r"((r)[9]),  "=r"((r)[10]), "=r"((r)[11]), \
          "=r"((r)[12]), "=r"((r)[13]), "=r"((r)[14]), "=r"((r)[15]), \
          "=r"((r)[16]), "=r"((r)[17]), "=r"((r)[18]), "=r"((r)[19]), \
          "=r"((r)[20]), "=r"((r)[21]), "=r"((r)[22]), "=r"((r)[23]), \
          "=r"((r)[24]), "=r"((r)[25]), "=r"((r)[26]), "=r"((r)[27]), \
          "=r"((r)[28]), "=r"((r)[29]), "=r"((r)[30]), "=r"((r)[31]) \
        : "r"(addr))
#endif  // HAS_TCGEN05

// ---------------- Kernel 0: build all 3 pre-swizzled W images in one pass ----------------
__global__ void k0_wsplit(const float* __restrict__ w) {
    int i = blockIdx.x * blockDim.x + threadIdx.x;      // 0..4095
    if (i == 0) g_done = 0;                             // reset last-block counter
    int c = i >> 9, e = (i >> 3) & 63, k16 = i & 7;
    const float4* src = reinterpret_cast<const float4*>(w + (size_t)e * DD + c * 64 + k16 * 8);
    float4 a = src[0], b = src[1];
    float f[8] = {a.x, a.y, a.z, a.w, b.x, b.y, b.z, b.w};
    uint32_t oh[4], om[4], ol[4];
#pragma unroll
    for (int q = 0; q < 4; q++) {
        __nv_bfloat16 h0 = __float2bfloat16(f[q*2]);
        __nv_bfloat16 h1 = __float2bfloat16(f[q*2+1]);
        float r0 = f[q*2]   - __bfloat162float(h0);
        float r1 = f[q*2+1] - __bfloat162float(h1);
        __nv_bfloat16 m0 = __float2bfloat16(r0);
        __nv_bfloat16 m1 = __float2bfloat16(r1);
        float l0 = r0 - __bfloat162float(m0);
        float l1 = r1 - __bfloat162float(m1);
        oh[q] = pack_bf2(h0, h1);
        om[q] = pack_bf2(m0, m1);
        ol[q] = pack_bf2(__float2bfloat16(l0), __float2bfloat16(l1));
    }
    uint32_t sw = sw128((uint32_t)e * 128 + k16 * 16);
    uint32_t base = c * B_STAGE_B;
    *reinterpret_cast<uint4*>(g_wimg + base + 0 * B_TILE_B + sw) = make_uint4(oh[0], oh[1], oh[2], oh[3]);
    *reinterpret_cast<uint4*>(g_wimg + base + 1 * B_TILE_B + sw) = make_uint4(om[0], om[1], om[2], om[3]);
    *reinterpret_cast<uint4*>(g_wimg + base + 2 * B_TILE_B + sw) = make_uint4(ol[0], ol[1], ol[2], ol[3]);
}

// ---------------- Kernel 1: TMA-fed TS GEMM + fused mask/zero-fill ----------------
// One CTA == one batch b (TILE_M == NN).
__global__ __launch_bounds__(THREADS1, 2)
void k1_gemm(const float* __restrict__ x,
             const float* __restrict__ bias,
             float* __restrict__ out,
             const __grid_constant__ CUtensorMap xmap) {
#if HAS_TCGEN05
    extern __shared__ char sm[];
    const uint32_t smem_base = smem_u32(sm);
#define MB_SF(i) (smem_base + 16  + (uint32_t)(i)*8)
#define MB_E(i)  (smem_base + 48  + (uint32_t)(i)*8)
#define MB_BF(i) (smem_base + 80  + (uint32_t)(i)*8)
#define MB_XF(i) (smem_base + 96  + (uint32_t)(i)*8)
#define MB_XR(i) (smem_base + 120 + (uint32_t)(i)*8)
    uint32_t* bitmap = reinterpret_cast<uint32_t*>(sm + 192);   // 2x u32 mask
    float* bias_s = reinterpret_cast<float*>(sm + 256);
    const uint32_t b0_abs = (smem_base + 1024 + 1023) & ~1023u;
    const uint32_t xs_abs = b0_abs + 2 * B_STAGE_B;
    char* xs_ptr = sm + (xs_abs - smem_base);

    const int tid = threadIdx.x;
    const int wid = tid >> 5, lid = tid & 31;
    const int bno = blockIdx.x;                    // batch index
    const long rowbase = (long)bno * TILE_M;

    if (wid == 8) {
        T5_ALLOC(smem_base, TMEM_COLS);
        T5_RELINQ();
    }
    if (tid == 0) {
#pragma unroll
        for (int i = 0; i < 4; i++) { mbar_init(MB_SF(i), 8); mbar_init(MB_E(i), 1); }
        mbar_init(MB_BF(0), 1); mbar_init(MB_BF(1), 1);
#pragma unroll
        for (int i = 0; i < 3; i++) { mbar_init(MB_XF(i), 1); mbar_init(MB_XR(i), 8); }
        bitmap[0] = 0; bitmap[1] = 0;
    }
    if (tid < EE) bias_s[tid] = bias[tid];
    __syncthreads();
    const uint32_t tmem = *reinterpret_cast<uint32_t*>(sm);

    if (wid < 8) {
        // ===== converters: LDS from TMA-staged xs -> 3x bf16 -> TMEM (A ring 4-deep) =====
        const int awid = wid & 3;               // subpartition
        const int kh   = wid >> 2;              // 16-k half of the 32-k chunk
        const int row  = awid * 32 + lid;
        const uint32_t woff = (uint32_t)awid << 21;
        const char* xrow = xs_ptr + row * 128;
        const uint32_t rsw = (uint32_t)(row & 7);

        uint32_t xmask = 0;        // xf parities per xs stage (init 0)
        uint32_t emask = 0xF;      // e parities per A stage (init 1)
        int sx = 0;
        for (int c = 0; c < ACH; c++) {
            const int s = c & 3;
            mbar_wait(MB_XF(sx), (xmask >> sx) & 1); xmask ^= 1u << sx;

            const char* xb = xrow + sx * XS_TILE_B;
            float4 f4[4];
#pragma unroll
            for (int i = 0; i < 4; i++)
                f4[i] = *reinterpret_cast<const float4*>(
                    xb + (((uint32_t)(kh * 4 + i) ^ rsw) << 4));

            // convert fully BEFORE the e-wait (off the critical section)
            uint32_t o0[8], o1[8], o2[8];
#pragma unroll
            for (int i = 0; i < 4; i++) {
                float4 v = f4[i];
#pragma unroll
                for (int p = 0; p < 2; p++) {
                    float a0 = p ? v.z : v.x;
                    float a1 = p ? v.w : v.y;
                    __nv_bfloat162 H = __float22bfloat162_rn(make_float2(a0, a1));
                    float2 Hf = __bfloat1622float2(H);
                    float r0 = a0 - Hf.x, r1 = a1 - Hf.y;
                    __nv_bfloat162 M = __float22bfloat162_rn(make_float2(r0, r1));
                    float2 Mf = __bfloat1622float2(M);
                    __nv_bfloat162 L = __float22bfloat162_rn(make_float2(r0 - Mf.x, r1 - Mf.y));
                    o0[i * 2 + p] = *reinterpret_cast<uint32_t*>(&H);
                    o1[i * 2 + p] = *reinterpret_cast<uint32_t*>(&M);
                    o2[i * 2 + p] = *reinterpret_cast<uint32_t*>(&L);
                }
            }
            __syncwarp();
            if (elect1()) mbar_arrive(MB_XR(sx));          // xs stage free early
            sx = (sx == 2) ? 0 : sx + 1;

            mbar_wait(MB_E(s), (emask >> s) & 1); emask ^= 1u << s;   // A stage free
            const uint32_t acol = tmem + TM_A + s * 48 + woff + kh * 8;
            STTM8(acol + 0,  o0);
            STTM8(acol + 16, o1);
            STTM8(acol + 32, o2);
            T5_WAIT_ST();
            T5_FENCE_BEFORE();
            if (elect1()) mbar_arrive(MB_SF(s));
        }

        // ===== epilogue =====
        if (wid >= 4) {
            // warps 4-7: zero-fill second half of this batch's output slab
            if (out) {
                float4* o4 = reinterpret_cast<float4*>(out) + (size_t)bno * 2048;
                const float4 z = make_float4(0.f, 0.f, 0.f, 0.f);
                const int t = (wid - 4) * 32 + lid;
#pragma unroll
                for (int i = 8; i < 16; i++)
                    o4[i * 128 + t] = z;
            }
        } else {
            // warps 0-3 (128 threads, one per seq position): softmax + mask + first half fill
            const int n = wid * 32 + lid;        // seq position 0..127
            mbar_wait(MB_E(3), 1);
            T5_FENCE_AFTER();

            float vals[EE];
            {
                uint32_t a[32];
                LDTM32(a, tmem + TM_D);
                T5_WAIT_LD();
#pragma unroll
                for (int e = 0; e < 32; e++)
                    vals[e] = __uint_as_float(a[e]) + bias_s[e];
                LDTM32(a, tmem + TM_D + 32);
                T5_WAIT_LD();
#pragma unroll
                for (int e = 0; e < 32; e++)
                    vals[32 + e] = __uint_as_float(a[e]) + bias_s[32 + e];
            }
            T5_FENCE_BEFORE();

            float bv = vals[0];
            int be = 0;
#pragma unroll
            for (int e = 1; e < EE; e++)
                if (vals[e] > bv) { bv = vals[e]; be = e; }
            float s = 0.f;
#pragma unroll
            for (int e = 0; e < EE; e++)
                s += __expf(vals[e] - bv);
            float p0 = __expf(vals[0] - bv) / s;

            // fused k2: membership bitmap over argmax values (be < 64)
            atomicOr(&bitmap[be >> 5], 1u << (be & 31));
            asm volatile("bar.sync 1, 128;" ::: "memory");

            if (n < EE) {
                uint32_t bit = (bitmap[n >> 5] >> (n & 31)) & 1u;
                // transposed layout [n][b] for coalesced k34 reads
                g_masked[(size_t)n * BB + bno] = bit ? p0 : 0.f;
            }

            // first half of the zero-fill
            if (out) {
                float4* o4 = reinterpret_cast<float4*>(out) + (size_t)bno * 2048;
                const float4 z = make_float4(0.f, 0.f, 0.f, 0.f);
                const int t = wid * 32 + lid;
#pragma unroll
                for (int i = 0; i < 8; i++)
                    o4[i * 128 + t] = z;
            }
        }
    } else {
        // ===== ctrl warp (wid 8): x 2D-TMA + B bulk TMA + MMA =====
        if (elect1()) {
            const int rb32 = (int)rowbase;
            // prologue: stage x chunks 0..2 and B chunks 0..1
#pragma unroll
            for (int p = 0; p < 3; p++) {
                arrive_expect_tx(MB_XF(p), XS_TILE_B);
                tma2d(xs_abs + p * XS_TILE_B, &xmap, p * 32, rb32, MB_XF(p));
            }
            arrive_expect_tx(MB_BF(0), B_STAGE_B);
            bulk_g2s(b0_abs, g_wimg, B_STAGE_B, MB_BF(0));
            arrive_expect_tx(MB_BF(1), B_STAGE_B);
            bulk_g2s(b0_abs + B_STAGE_B, g_wimg + B_STAGE_B, B_STAGE_B, MB_BF(1));

            uint64_t bd0[3], bd1[3];
#pragma unroll
            for (int t = 0; t < 3; t++) {
                bd0[t] = make_desc_sw128(b0_abs + t * B_TILE_B);
                bd1[t] = make_desc_sw128(b0_abs + B_STAGE_B + t * B_TILE_B);
            }
            const int ta[6] = {0, 0, 1, 1, 0, 2};
            const int tb[6] = {0, 1, 0, 1, 2, 0};

            uint32_t smask = 0;    // sf parities (init 0)
            uint32_t bmask = 0;    // bf parities (init 0)
            uint32_t xrmask = 0;   // xr parities (init 0)
            uint32_t ebmask = 0;   // e parities for B-prefetch (stages 1,3; init 0)
            for (int c = 0; c < ACH; c++) {
                const int s  = c & 3;
                const int cb = c >> 1;

                mbar_wait(MB_SF(s), (smask >> s) & 1); smask ^= 1u << s;
                if ((c & 1) == 0) {
                    const int bs = cb & 1;
                    mbar_wait(MB_BF(bs), (bmask >> bs) & 1); bmask ^= 1u << bs;
                }
                T5_FENCE_AFTER();

                const uint32_t abase = tmem + TM_A + s * 48;
                const uint64_t* bd = (cb & 1) ? bd1 : bd0;
                const int koff = (c & 1) * 4;
#pragma unroll
                for (int ks = 0; ks < 2; ks++) {
#pragma unroll
                    for (int t = 0; t < 6; t++) {
                        uint32_t a = abase + ta[t] * 16 + ks * 8;
                        uint64_t b = bd[tb[t]] + koff + ks * 2;
                        uint32_t en = !(c == 0 && ks == 0 && t == 0);
                        mma_ts_f16(tmem + TM_D, a, b, IDESC, en);
                    }
                }
                t5_commit(MB_E(s));

                // x prefetch chunk c+3 into stage c%3 (xr(c) already arrived: sf(c) done)
                if (c + 3 < ACH) {
                    const int sx = c % 3;
                    mbar_wait(MB_XR(sx), (xrmask >> sx) & 1); xrmask ^= 1u << sx;
                    arrive_expect_tx(MB_XF(sx), XS_TILE_B);
                    tma2d(xs_abs + sx * XS_TILE_B, &xmap, (c + 3) * 32, rb32, MB_XF(sx));
                }

                // B prefetch (2 A-chunks of lead)
                if ((c & 1) == 0 && c + 2 < ACH) {
                    const int cbn = cb + 1;
                    if (cbn >= 2) {
                        const int es = (c - 1) & 3;          // 1 or 3
                        const int ei = (es == 1) ? 0 : 1;
                        mbar_wait(MB_E(es), (ebmask >> ei) & 1); ebmask ^= 1u << ei;
                        arrive_expect_tx(MB_BF(cbn & 1), B_STAGE_B);
                        bulk_g2s(b0_abs + (cbn & 1) * B_STAGE_B,
                                 g_wimg + cbn * B_STAGE_B, B_STAGE_B, MB_BF(cbn & 1));
                    }
                }
            }
        }
    }

    __syncthreads();
    if (wid == 8) {
        T5_DEALLOC(tmem, TMEM_COLS);
    }
#else
    // ---------------- portable fallback (generic-PTX compile phase only) ----------------
    __shared__ uint32_t fb_bitmap[2];
    __shared__ float fb_p0[TILE_M];
    const int tid = threadIdx.x;
    const int bno = blockIdx.x;
    if (tid == 0) { fb_bitmap[0] = 0; fb_bitmap[1] = 0; }
    __syncthreads();
    if (tid < TILE_M) {
        fb_p0[tid] = 0.f;
        atomicOr(&fb_bitmap[0], 1u);
    }
    __syncthreads();
    if (tid < EE) g_masked[(size_t)tid * BB + bno] = fb_p0[tid];
    if (out && tid < TILE_M) {
        float4* o4 = reinterpret_cast<float4*>(out) + (size_t)bno * 2048;
        const float4 z = make_float4(0.f, 0.f, 0.f, 0.f);
        for (int i = 0; i < 16; i++) o4[i * 128 + tid] = z;
    }
    (void)x; (void)bias;
#endif
}

// ---------------- Kernel 34: column reduce + scatter + fused last-block loss ----------------
// One block per expert-column n.
__global__ void k34_denom_scatter(float* __restrict__ out, float* __restrict__ lossptr) {
    __shared__ float sv[256];
    __shared__ int   sc[256];
    __shared__ float sscale;
    __shared__ int   islast;
    const int n = blockIdx.x;
    const int t = threadIdx.x;

    float m[8];
    float s = 0.f;
    int cnt = 0;
#pragma unroll
    for (int k = 0; k < BB / 256; k++) {
        m[k] = g_masked[(size_t)n * BB + t + k * 256];
        s += m[k];
        cnt += (m[k] > 0.f);
    }
    sv[t] = s; sc[t] = cnt;
    __syncthreads();
    for (int off = 128; off >= 1; off >>= 1) {
        if (t < off) { sv[t] += sv[t + off]; sc[t] += sc[t + off]; }
        __syncthreads();
    }
    if (t == 0) {
        float dn = sv[0] + EPS;
        g_denom[n] = dn;
        g_load[n]  = sc[0];
        sscale = CAPACITY / dn;
    }
    __syncthreads();

    if (out) {
        const float scale = sscale;
#pragma unroll
        for (int k = 0; k < BB / 256; k++) {
            int b = t + k * 256;
            out[((size_t)b * NN + n) * EE] = m[k] * scale;
        }
    }

    if (lossptr) {
        // last-block loss computation
        __threadfence();
        if (t == 0) islast = (atomicAdd(&g_done, 1) == EE - 1);
        __syncthreads();
        if (islast) {
            __shared__ double sA[EE], sB[EE], sC[EE], sD[EE];
            __threadfence();   // acquire-side: make peers' denom/load visible
            if (t < EE) {
                double dn = (double)(*(volatile float*)&g_denom[t]);
                double ld = (double)(*(volatile int*)&g_load[t]);
                double S  = dn - (double)EPS;
                double imp = (double)CAPACITY * S / dn;
                sA[t] = imp; sB[t] = imp * imp;
                sC[t] = ld;  sD[t] = ld * ld;
            }
            __syncthreads();
            if (t < 32) {
                double a = sA[t] + sA[t + 32];
                double b = sB[t] + sB[t + 32];
                double c = sC[t] + sC[t + 32];
                double d = sD[t] + sD[t + 32];
#pragma unroll
                for (int off = 16; off >= 1; off >>= 1) {
                    a += __shfl_xor_sync(0xffffffffu, a, off);
                    b += __shfl_xor_sync(0xffffffffu, b, off);
                    c += __shfl_xor_sync(0xffffffffu, c, off);
                    d += __shfl_xor_sync(0xffffffffu, d, off);
                }
                if (t == 0) {
                    const double M = (double)(NN * EE);
                    double mean_i = a / M;
                    double var_i  = (b - a * a / M) / (M - 1.0);
                    double cv_i   = var_i / (mean_i * mean_i + 1e-10);
                    double mean_l = c / M;
                    double var_l  = (d - c * c / M) / (M - 1.0);
                    double cv_l   = var_l / (mean_l * mean_l + 1e-10);
                    *lossptr = (float)(cv_i + cv_l);
                }
            }
        }
    }
}

// host-side tensor map encode via driver entry point (no -lcuda link needed)
typedef CUresult (*EncodeTiledFn)(
    CUtensorMap*, CUtensorMapDataType, cuuint32_t, void*,
    const cuuint64_t*, const cuuint64_t*, const cuuint32_t*, const cuuint32_t*,
    CUtensorMapInterleave, CUtensorMapSwizzle, CUtensorMapL2promotion,
    CUtensorMapFloatOOBfill);

extern "C" void kernel_launch(void* const* d_in, const int* in_sizes, int n_in,
                              void* d_out, int out_size) {
    const float* x    = (const float*)d_in[0];
    const float* w    = (const float*)d_in[1];
    const float* bias = (const float*)d_in[2];
    float* out = (float*)d_out;

    const long total = (long)BB * NN * EE;        // 16777216
    float* gs_out = ((long)out_size >= total) ? out : nullptr;
    float* lossptr = nullptr;
    if ((long)out_size > total)       lossptr = out + total;   // gs + loss
    else if (!gs_out)                 lossptr = out;            // loss only

    // Build the x tensor map: fp32 [512 x 262144], box [32 x 128], SW128.
    CUtensorMap xmap;
    {
        EncodeTiledFn fn = nullptr;
        cudaDriverEntryPointQueryResult qres;
        cudaGetDriverEntryPoint("cuTensorMapEncodeTiled", (void**)&fn,
                                cudaEnableDefault, &qres);
        cuuint64_t dims[2]    = {DD, ROWS};
        cuuint64_t strides[1] = {DD * sizeof(float)};
        cuuint32_t box[2]     = {32, TILE_M};
        cuuint32_t estr[2]    = {1, 1};
        fn(&xmap, CU_TENSOR_MAP_DATA_TYPE_FLOAT32, 2, (void*)x,
           dims, strides, box, estr,
           CU_TENSOR_MAP_INTERLEAVE_NONE, CU_TENSOR_MAP_SWIZZLE_128B,
           CU_TENSOR_MAP_L2_PROMOTION_L2_128B, CU_TENSOR_MAP_FLOAT_OOB_FILL_NONE);
    }

    cudaFuncSetAttribute(k1_gemm, cudaFuncAttributeMaxDynamicSharedMemorySize, SMEM_TC);

    // 3 launches per iteration: k0, k1, k34
    k0_wsplit<<<16, 256>>>(w);
    k1_gemm<<<ROWS / TILE_M, THREADS1, SMEM_TC>>>(x, bias, gs_out, xmap);
    k34_denom_scatter<<<EE, 256>>>(gs_out, lossptr);
}